// round 2
// baseline (speedup 1.0000x reference)
#include <cuda_runtime.h>

#define HID 2048
#define G3  (3 * HID)          // 6144
#define ROWS (2 * G3)          // 12288 total dot products (gi rows then gh rows)
#define WARPS_PER_BLOCK 8
#define THREADS (WARPS_PER_BLOCK * 32)
#define NBLOCKS (ROWS / WARPS_PER_BLOCK)   // 1536

// Scratch: gate pre-activations. gi in [0,6144), gh in [6144,12288).
__device__ float g_gates[ROWS];
// Completion counter for last-block-done epilogue. Zero-initialized by the
// runtime at module load; the epilogue block resets it to 0 every call so
// graph replays are deterministic.
__device__ unsigned int g_done;

__global__ void __launch_bounds__(THREADS) gru_fused_kernel(
    const int* __restrict__ inp,
    const float* __restrict__ hidden,
    const float* __restrict__ emb,
    const float* __restrict__ w_ih,
    const float* __restrict__ w_hh,
    const float* __restrict__ b_ih,
    const float* __restrict__ b_hh,
    float* __restrict__ out,
    int out_size)
{
    // ---- GEMV phase: one warp per output row ----
    int gwarp = (blockIdx.x * THREADS + threadIdx.x) >> 5;
    int lane  = threadIdx.x & 31;

    const float* W;
    const float* v;
    int row;
    if (gwarp < G3) {
        // gi = w_ih @ x, x = emb[input]
        W = w_ih;
        v = emb + (size_t)inp[0] * HID;  // little-endian: low word valid for i32 or i64 index
        row = gwarp;
    } else {
        // gh = w_hh @ h
        W = w_hh;
        v = hidden;
        row = gwarp - G3;
    }

    const float4* wr = (const float4*)(W + (size_t)row * HID);
    const float4* vr = (const float4*)v;

    float acc = 0.0f;
#pragma unroll
    for (int i = 0; i < HID / 4 / 32; ++i) {   // 16 fully-unrolled iterations
        float4 a = wr[lane + 32 * i];
        float4 b = vr[lane + 32 * i];
        acc = fmaf(a.x, b.x, acc);
        acc = fmaf(a.y, b.y, acc);
        acc = fmaf(a.z, b.z, acc);
        acc = fmaf(a.w, b.w, acc);
    }

#pragma unroll
    for (int off = 16; off > 0; off >>= 1)
        acc += __shfl_xor_sync(0xFFFFFFFFu, acc, off);

    if (lane == 0) g_gates[gwarp] = acc;

    // ---- last-block-done epilogue ----
    __threadfence();          // make g_gates writes visible device-wide
    __syncthreads();          // all warps of this block have stored

    __shared__ unsigned int s_last;
    if (threadIdx.x == 0)
        s_last = (atomicAdd(&g_done, 1u) == (unsigned)(NBLOCKS - 1));
    __syncthreads();

    if (!s_last) return;

    __threadfence();          // acquire: see every block's g_gates stores

    // Gate math: 2048 elements over 256 threads = 8 per thread.
    for (int j = threadIdx.x; j < HID; j += THREADS) {
        float i_r = g_gates[j          ] + b_ih[j          ];
        float i_z = g_gates[j +   HID  ] + b_ih[j +   HID  ];
        float i_n = g_gates[j + 2*HID  ] + b_ih[j + 2*HID  ];
        float h_r = g_gates[G3 + j         ] + b_hh[j         ];
        float h_z = g_gates[G3 + j +  HID  ] + b_hh[j +  HID  ];
        float h_n = g_gates[G3 + j + 2*HID ] + b_hh[j + 2*HID ];

        float r = 1.0f / (1.0f + __expf(-(i_r + h_r)));
        float z = 1.0f / (1.0f + __expf(-(i_z + h_z)));
        float n = tanhf(i_n + r * h_n);
        float h = hidden[j];
        float h_new = (1.0f - z) * n + z * h;

        out[j] = h_new;
        if (out_size >= 2 * HID) out[j + HID] = h_new;  // (out, h_new) identical
    }

    // Reset counter for the next graph replay.
    __syncthreads();
    if (threadIdx.x == 0) {
        __threadfence();
        g_done = 0u;
    }
}

extern "C" void kernel_launch(void* const* d_in, const int* in_sizes, int n_in,
                              void* d_out, int out_size)
{
    const int*   inp    = (const int*)  d_in[0];
    const float* hidden = (const float*)d_in[1];
    const float* emb    = (const float*)d_in[2];
    const float* w_ih   = (const float*)d_in[3];
    const float* w_hh   = (const float*)d_in[4];
    const float* b_ih   = (const float*)d_in[5];
    const float* b_hh   = (const float*)d_in[6];
    float* out = (float*)d_out;

    gru_fused_kernel<<<NBLOCKS, THREADS>>>(inp, hidden, emb, w_ih, w_hh,
                                           b_ih, b_hh, out, out_size);
}

// round 4
// speedup vs baseline: 1.0784x; 1.0784x over previous
#include <cuda_runtime.h>

#define HID 2048
#define G3  (3 * HID)            // 6144
#define ROWS (2 * G3)            // 12288 dot products
#define THREADS 256
#define WARPS_PER_BLOCK 8
#define ROWS_PER_BLOCK WARPS_PER_BLOCK
#define BLOCKS_PER_MAT (G3 / ROWS_PER_BLOCK)   // 768
#define NBLOCKS (2 * BLOCKS_PER_MAT)           // 1536
#define VEC4 (HID / 4)           // 512 float4 in the shared vector

// Gate pre-activations: gi in [0,6144), gh in [6144,12288).
__device__ float g_gates[ROWS];
// Last-block-done counter (zero-init at load; reset each call for graph replay).
__device__ unsigned int g_done;

__global__ void __launch_bounds__(THREADS) gru_fused_kernel(
    const int* __restrict__ inp,
    const float* __restrict__ hidden,
    const float* __restrict__ emb,
    const float* __restrict__ w_ih,
    const float* __restrict__ w_hh,
    const float* __restrict__ b_ih,
    const float* __restrict__ b_hh,
    float* __restrict__ out,
    int out_size)
{
    __shared__ float4 sv[VEC4];          // 8KB vector shared by this block's rows

    const int wid  = threadIdx.x >> 5;
    const int lane = threadIdx.x & 31;

    // Interleave the two matrices: even blocks -> w_ih, odd blocks -> w_hh.
    const bool is_ih = ((blockIdx.x & 1) == 0);
    const float* W = is_ih ? w_ih : w_hh;
    const float* v = is_ih ? (emb + (size_t)inp[0] * HID) : hidden;
    const int mat_row0 = (blockIdx.x >> 1) * ROWS_PER_BLOCK;

    // Stage v into shared memory (512 float4 over 256 threads = 2 each).
    {
        const float4* v4 = (const float4*)v;
        sv[threadIdx.x]           = v4[threadIdx.x];
        sv[threadIdx.x + THREADS] = v4[threadIdx.x + THREADS];
    }
    __syncthreads();

    // ---- GEMV: one warp per row, all 16 W loads front-batched ----
    const int row = mat_row0 + wid;
    const float4* wr = (const float4*)(W + (size_t)row * HID);

    float4 a[16];
#pragma unroll
    for (int i = 0; i < 16; ++i)
        a[i] = wr[lane + 32 * i];

    float acc = 0.0f;
#pragma unroll
    for (int i = 0; i < 16; ++i) {
        float4 b4 = sv[lane + 32 * i];
        acc = fmaf(a[i].x, b4.x, acc);
        acc = fmaf(a[i].y, b4.y, acc);
        acc = fmaf(a[i].z, b4.z, acc);
        acc = fmaf(a[i].w, b4.w, acc);
    }

#pragma unroll
    for (int off = 16; off > 0; off >>= 1)
        acc += __shfl_xor_sync(0xFFFFFFFFu, acc, off);

    const int grow = (is_ih ? 0 : G3) + row;
    if (lane == 0) g_gates[grow] = acc;

    // ---- last-block-done epilogue ----
    __threadfence();
    __syncthreads();

    __shared__ unsigned int s_last;
    if (threadIdx.x == 0)
        s_last = (atomicAdd(&g_done, 1u) == (unsigned)(NBLOCKS - 1));
    __syncthreads();
    if (!s_last) return;

    __threadfence();   // acquire all blocks' g_gates stores

    for (int j = threadIdx.x; j < HID; j += THREADS) {
        float i_r = g_gates[j          ] + b_ih[j          ];
        float i_z = g_gates[j +   HID  ] + b_ih[j +   HID  ];
        float i_n = g_gates[j + 2*HID  ] + b_ih[j + 2*HID  ];
        float h_r = g_gates[G3 + j         ] + b_hh[j         ];
        float h_z = g_gates[G3 + j +  HID  ] + b_hh[j +  HID  ];
        float h_n = g_gates[G3 + j + 2*HID ] + b_hh[j + 2*HID ];

        float r = 1.0f / (1.0f + __expf(-(i_r + h_r)));
        float z = 1.0f / (1.0f + __expf(-(i_z + h_z)));
        float n = tanhf(i_n + r * h_n);
        float h = hidden[j];
        float h_new = (1.0f - z) * n + z * h;

        out[j] = h_new;
        if (out_size >= 2 * HID) out[j + HID] = h_new;  // (out, h_new) identical
    }

    __syncthreads();
    if (threadIdx.x == 0) {
        __threadfence();
        g_done = 0u;     // reset for next graph replay
    }
}

extern "C" void kernel_launch(void* const* d_in, const int* in_sizes, int n_in,
                              void* d_out, int out_size)
{
    const int*   inp    = (const int*)  d_in[0];
    const float* hidden = (const float*)d_in[1];
    const float* emb    = (const float*)d_in[2];
    const float* w_ih   = (const float*)d_in[3];
    const float* w_hh   = (const float*)d_in[4];
    const float* b_ih   = (const float*)d_in[5];
    const float* b_hh   = (const float*)d_in[6];
    float* out = (float*)d_out;

    gru_fused_kernel<<<NBLOCKS, THREADS>>>(inp, hidden, emb, w_ih, w_hh,
                                           b_ih, b_hh, out, out_size);
}